// round 6
// baseline (speedup 1.0000x reference)
#include <cuda_runtime.h>
#include <cuda_bf16.h>
#include <cstdint>

#define B_ 256
#define T_ 128
#define N_ 512
#define H_ 128
#define MTOT (B_*T_)   /* 32768 */
#define GATE (4*H_)    /* 512 */

// ---------------- scratch (device globals: no allocation allowed) ----------------
__device__ float          g_alpha[B_*N_];
__device__ __nv_bfloat16  g_Ah[MTOT*N_];
__device__ __nv_bfloat16  g_Al[MTOT*N_];
__device__ __nv_bfloat16  g_Wh[GATE*N_];
__device__ __nv_bfloat16  g_Wl[GATE*N_];
__device__ float          g_G[(size_t)MTOT*GATE];

// ---------------- helpers ----------------
__device__ __forceinline__ uint32_t smem_u32(const void* p){
    uint32_t a;
    asm("{ .reg .u64 t; cvta.to.shared.u64 t, %1; cvt.u32.u64 %0, t; }" : "=r"(a) : "l"(p));
    return a;
}
// f32x2 packed math (base ISA on sm_100+; ptxas accepted it in R5)
__device__ __forceinline__ unsigned long long fma2(unsigned long long a,
                                                   unsigned long long b,
                                                   unsigned long long c){
    unsigned long long d;
    asm("fma.rn.f32x2 %0, %1, %2, %3;" : "=l"(d) : "l"(a), "l"(b), "l"(c));
    return d;
}
__device__ __forceinline__ unsigned long long pack2(float x, float y){
    unsigned long long u;
    asm("mov.b64 %0, {%1, %2};" : "=l"(u) : "f"(x), "f"(y));
    return u;
}
__device__ __forceinline__ float2 unpack2(unsigned long long u){
    float2 v;
    asm("mov.b64 {%0, %1}, %2;" : "=f"(v.x), "=f"(v.y) : "l"(u));
    return v;
}
__device__ __forceinline__ float sigm(float x){ return 1.f / (1.f + __expf(-x)); }

#define LDSM4(r0, r1, r2, r3, addr) \
    asm volatile("ldmatrix.sync.aligned.m8n8.x4.shared.b16 {%0,%1,%2,%3}, [%4];" \
                 : "=r"(r0), "=r"(r1), "=r"(r2), "=r"(r3) : "r"(addr))

#define MMA16816(c, a, b0, b1) \
    asm volatile("mma.sync.aligned.m16n8k16.row.col.f32.bf16.bf16.f32 " \
                 "{%0,%1,%2,%3}, {%4,%5,%6,%7}, {%8,%9}, {%0,%1,%2,%3};" \
                 : "+f"((c)[0]), "+f"((c)[1]), "+f"((c)[2]), "+f"((c)[3]) \
                 : "r"((a)[0]), "r"((a)[1]), "r"((a)[2]), "r"((a)[3]), \
                   "r"(b0), "r"(b1))

__device__ __forceinline__ void cp16(uint32_t s, const void* g){
    asm volatile("cp.async.cg.shared.global [%0], [%1], 16;" :: "r"(s), "l"(g));
}
__device__ __forceinline__ void cp_commit(){
    asm volatile("cp.async.commit_group;" ::: "memory");
}
template<int N> __device__ __forceinline__ void cp_wait(){
    asm volatile("cp.async.wait_group %0;" :: "n"(N) : "memory");
}

// ==================================================================
// K1: alpha[b,n] = softmax_n( sum_t X[b,t,n] * w_x[t] )   (time-invariant!)
// score = x_score + per-batch scalar  =>  softmax shift-invariance kills
// the h/c dependence; attn_b, w_h, w_s are dead.
// ==================================================================
__global__ void __launch_bounds__(512) k_alpha(const float* __restrict__ X,
                                               const float* __restrict__ attn_w){
    __shared__ float wx[T_];
    __shared__ float red[N_];
    int b = blockIdx.x, n = threadIdx.x;
    if (n < T_) wx[n] = attn_w[2 * H_ + n];
    __syncthreads();
    const float* xb = X + (size_t)b * T_ * N_ + n;
    float s = 0.f;
#pragma unroll 8
    for (int t = 0; t < T_; t++) s += xb[(size_t)t * N_] * wx[t];
    red[n] = s; __syncthreads();
    for (int off = N_ / 2; off > 0; off >>= 1){
        if (n < off){ float o = red[n + off]; if (o > red[n]) red[n] = o; }
        __syncthreads();
    }
    float mx = red[0]; __syncthreads();
    float e = __expf(s - mx);
    red[n] = e; __syncthreads();
    for (int off = N_ / 2; off > 0; off >>= 1){
        if (n < off) red[n] += red[n + off];
        __syncthreads();
    }
    g_alpha[(size_t)b * N_ + n] = e / red[0];
}

// ==================================================================
// K2b: bf16 hi/lo split of w_ih
// ==================================================================
__global__ void k_wsplit(const float* __restrict__ w){
    int i = blockIdx.x * blockDim.x + threadIdx.x;  // 512*512 total
    float v = w[i];
    __nv_bfloat16 h = __float2bfloat16_rn(v);
    g_Wh[i] = h;
    g_Wl[i] = __float2bfloat16_rn(v - __bfloat162float(h));
}

// ==================================================================
// K2: Xt = alpha * X  (output 1, fp32) + bf16 hi/lo copies for the GEMM
// ==================================================================
__global__ void __launch_bounds__(256) k_xt(const float4* __restrict__ X4,
                                            float4* __restrict__ O4){
    int i = blockIdx.x * 256 + threadIdx.x;       // 4,194,304 float4s
    float4 x = X4[i];
    int b  = i >> 14;                              // / (T*N/4)
    int n4 = i & 127;                              // float4 col within row
    float4 a = ((const float4*)g_alpha)[b * (N_ / 4) + n4];
    float4 r;
    r.x = a.x * x.x; r.y = a.y * x.y; r.z = a.z * x.z; r.w = a.w * x.w;
    O4[i] = r;
    __nv_bfloat16 hx = __float2bfloat16_rn(r.x), hy = __float2bfloat16_rn(r.y);
    __nv_bfloat16 hz = __float2bfloat16_rn(r.z), hw = __float2bfloat16_rn(r.w);
    __nv_bfloat16 lx = __float2bfloat16_rn(r.x - __bfloat162float(hx));
    __nv_bfloat16 ly = __float2bfloat16_rn(r.y - __bfloat162float(hy));
    __nv_bfloat16 lz = __float2bfloat16_rn(r.z - __bfloat162float(hz));
    __nv_bfloat16 lw = __float2bfloat16_rn(r.w - __bfloat162float(hw));
    union { __nv_bfloat162 h2[2]; uint2 u; } uh, ul;
    uh.h2[0] = __halves2bfloat162(hx, hy); uh.h2[1] = __halves2bfloat162(hz, hw);
    ul.h2[0] = __halves2bfloat162(lx, ly); ul.h2[1] = __halves2bfloat162(lz, lw);
    ((uint2*)g_Ah)[i] = uh.u;
    ((uint2*)g_Al)[i] = ul.u;
}

// ==================================================================
// K3: G = Xt @ w_ih^T via mma.sync bf16 (HMMA), hi/lo compensated.
//     CTA tile 128x128, K-chunk 32, cp.async double buffer.
//     smem rows: 32 bf16 = 64B at pitch 80B -> ldmatrix conflict-free
//     (20-bank row stride permutes 8 rows over all 32 banks, no swizzle).
// ==================================================================
#define TILE_B  (128*80)       /* 10240 bytes per tile */
#define STAGE_B (4*TILE_B)     /* 40960 bytes per stage */
#define SM_K3   (2*STAGE_B)    /* 81920 */

__device__ __forceinline__ void cp_tile(uint32_t sdst, const __nv_bfloat16* __restrict__ g,
                                        int row0, int kc, int tid){
#pragma unroll
    for (int i = 0; i < 2; i++){
        int id = tid + i * 256;            // 512 x 16B chunks
        int row = id >> 2, c = id & 3;
        cp16(sdst + row * 80 + c * 16,
             g + (size_t)(row0 + row) * 512 + kc * 32 + c * 8);
    }
}

__global__ void __launch_bounds__(256, 2) k_gemm(){
    extern __shared__ char sm[];
    uint32_t smb = smem_u32(sm);
    int tid = threadIdx.x, lane = tid & 31, wid = tid >> 5;
    int nt = blockIdx.x, mt = blockIdx.y;      // x fastest: 4 nt share A panel in L2
    int wm = wid & 3, wn = wid >> 2;           // 4 m-warps x 2 n-warps
    int m0 = wm * 32, n0 = wn * 64;

    float C[2][8][4];
#pragma unroll
    for (int a = 0; a < 2; a++)
#pragma unroll
        for (int b = 0; b < 8; b++)
#pragma unroll
            for (int c = 0; c < 4; c++) C[a][b][c] = 0.f;

    // prologue: stage 0
    {
        uint32_t s0 = smb;
        cp_tile(s0,              g_Ah, mt * 128, 0, tid);
        cp_tile(s0 + TILE_B,     g_Al, mt * 128, 0, tid);
        cp_tile(s0 + 2 * TILE_B, g_Wh, nt * 128, 0, tid);
        cp_tile(s0 + 3 * TILE_B, g_Wl, nt * 128, 0, tid);
        cp_commit();
    }

    // per-lane ldmatrix address components (constant over k loop)
    int arow  = m0 + (lane & 15);
    int akoff = (lane & 16) ? 16 : 0;          // k-halves for A
    int nrow  = n0 + (lane & 7) + ((lane & 16) ? 8 : 0);
    int bkoff = (lane & 8) ? 16 : 0;           // k-halves for B

    for (int kc = 0; kc < 16; kc++){
        if (kc < 15){
            uint32_t sn = smb + ((kc + 1) & 1) * STAGE_B;
            cp_tile(sn,              g_Ah, mt * 128, kc + 1, tid);
            cp_tile(sn + TILE_B,     g_Al, mt * 128, kc + 1, tid);
            cp_tile(sn + 2 * TILE_B, g_Wh, nt * 128, kc + 1, tid);
            cp_tile(sn + 3 * TILE_B, g_Wl, nt * 128, kc + 1, tid);
            cp_commit();
            cp_wait<1>();
        } else {
            cp_wait<0>();
        }
        __syncthreads();

        uint32_t sA  = smb + (kc & 1) * STAGE_B;
        uint32_t sAl = sA + TILE_B;
        uint32_t sBh = sA + 2 * TILE_B;
        uint32_t sBl = sA + 3 * TILE_B;

#pragma unroll
        for (int ks = 0; ks < 2; ks++){
            uint32_t ah[2][4], al[2][4];
            uint32_t ka = ks * 32 + akoff;
            LDSM4(ah[0][0], ah[0][1], ah[0][2], ah[0][3], sA  + arow * 80 + ka);
            LDSM4(ah[1][0], ah[1][1], ah[1][2], ah[1][3], sA  + (arow + 16) * 80 + ka);
            LDSM4(al[0][0], al[0][1], al[0][2], al[0][3], sAl + arow * 80 + ka);
            LDSM4(al[1][0], al[1][1], al[1][2], al[1][3], sAl + (arow + 16) * 80 + ka);
            uint32_t kb = ks * 32 + bkoff;
#pragma unroll
            for (int nbp = 0; nbp < 4; nbp++){
                uint32_t bh[4], bl[4];
                uint32_t boff = (nrow + nbp * 16) * 80 + kb;
                LDSM4(bh[0], bh[1], bh[2], bh[3], sBh + boff);
                LDSM4(bl[0], bl[1], bl[2], bl[3], sBl + boff);
#pragma unroll
                for (int mb = 0; mb < 2; mb++){
                    MMA16816(C[mb][nbp * 2],     ah[mb], bh[0], bh[1]);
                    MMA16816(C[mb][nbp * 2],     al[mb], bh[0], bh[1]);
                    MMA16816(C[mb][nbp * 2],     ah[mb], bl[0], bl[1]);
                    MMA16816(C[mb][nbp * 2 + 1], ah[mb], bh[2], bh[3]);
                    MMA16816(C[mb][nbp * 2 + 1], al[mb], bh[2], bh[3]);
                    MMA16816(C[mb][nbp * 2 + 1], ah[mb], bl[2], bl[3]);
                }
            }
        }
        __syncthreads();   // stage consumed; safe to overwrite next iter
    }

    // epilogue: C -> g_G (fp32, row = token, col = gate)
    int rbase = mt * 128 + m0 + (lane >> 2);
    int cbase = nt * 128 + n0 + (lane & 3) * 2;
#pragma unroll
    for (int mb = 0; mb < 2; mb++){
#pragma unroll
        for (int na = 0; na < 8; na++){
            float* p0 = g_G + (size_t)(rbase + mb * 16) * 512 + cbase + na * 8;
            float* p1 = p0 + 8 * 512;
            *(float2*)p0 = make_float2(C[mb][na][0], C[mb][na][1]);
            *(float2*)p1 = make_float2(C[mb][na][2], C[mb][na][3]);
        }
    }
}

// ==================================================================
// K4: recurrence. 128 CTAs x 2 batches, 512 threads (thread = gate j).
//     gates = G[b,t,:] + h @ w_hh^T + bias;  LSTM cell; Xe out.
//     w_hh row j: k 0..63 in smem (pitch 68 floats, conflict-free
//     LDS.128 phases), k 64..127 in regs as packed f32x2 pairs.
// ==================================================================
#define K4_WSP 68
#define K4_SMEM ((512*K4_WSP + 128 + 128 + 512 + 512) * 4)

__global__ void __launch_bounds__(512, 1) k_rec(const float* __restrict__ whh,
                                                const float* __restrict__ b_ih,
                                                const float* __restrict__ b_hh,
                                                float* __restrict__ Xe){
    extern __shared__ float smf[];
    float* ws  = smf;                  // 512*68
    float* hs0 = smf + 512 * K4_WSP;   // 128
    float* hs1 = hs0 + 128;            // 128
    float* gs0 = hs1 + 128;            // 512
    float* gs1 = gs0 + 512;            // 512
    int j = threadIdx.x;
    int b0 = blockIdx.x * 2, b1 = b0 + 1;

    for (int idx = j; idx < 512 * 64; idx += 512){
        int r = idx >> 6, k = idx & 63;
        ws[r * K4_WSP + k] = whh[r * 128 + k];
    }
    unsigned long long wr[32];
    {
        const float2* wp = (const float2*)(whh + (size_t)j * 128 + 64);
#pragma unroll
        for (int i = 0; i < 32; i++){ float2 v = wp[i]; wr[i] = pack2(v.x, v.y); }
    }
    float bias = b_ih[j] + b_hh[j];
    float c0 = 0.f, c1 = 0.f;
    if (j < 128){ hs0[j] = 0.f; hs1[j] = 0.f; }
    __syncthreads();

    const ulonglong2* wsv = (const ulonglong2*)(ws + (size_t)j * K4_WSP);
    const ulonglong2* h0v = (const ulonglong2*)hs0;
    const ulonglong2* h1v = (const ulonglong2*)hs1;
    const float* Gb0 = g_G + (size_t)b0 * T_ * 512 + j;
    const float* Gb1 = g_G + (size_t)b1 * T_ * 512 + j;
    float* xe0 = Xe + (size_t)b0 * T_ * H_;
    float* xe1 = Xe + (size_t)b1 * T_ * H_;

    for (int t = 0; t < T_; t++){
        float gv0 = Gb0[(size_t)t * 512];
        float gv1 = Gb1[(size_t)t * 512];
        unsigned long long a0 = 0ull, a1 = 0ull;
#pragma unroll
        for (int i = 0; i < 16; i++){              // k = 0..63 from smem
            ulonglong2 w2 = wsv[i];
            ulonglong2 hA = h0v[i], hB = h1v[i];
            a0 = fma2(w2.x, hA.x, a0); a0 = fma2(w2.y, hA.y, a0);
            a1 = fma2(w2.x, hB.x, a1); a1 = fma2(w2.y, hB.y, a1);
        }
#pragma unroll
        for (int i = 0; i < 16; i++){              // k = 64..127 from regs
            ulonglong2 hA = h0v[16 + i], hB = h1v[16 + i];
            a0 = fma2(wr[2 * i], hA.x, a0); a0 = fma2(wr[2 * i + 1], hA.y, a0);
            a1 = fma2(wr[2 * i], hB.x, a1); a1 = fma2(wr[2 * i + 1], hB.y, a1);
        }
        float2 s0 = unpack2(a0), s1 = unpack2(a1);
        gs0[j] = s0.x + s0.y + gv0 + bias;
        gs1[j] = s1.x + s1.y + gv1 + bias;
        __syncthreads();
        if (j < 128){
            float i0 = gs0[j], f0 = gs0[j + 128], g0 = gs0[j + 256], o0 = gs0[j + 384];
            float i1 = gs1[j], f1 = gs1[j + 128], g1 = gs1[j + 256], o1 = gs1[j + 384];
            c0 = sigm(f0) * c0 + sigm(i0) * tanhf(g0);
            c1 = sigm(f1) * c1 + sigm(i1) * tanhf(g1);
            float h0 = sigm(o0) * tanhf(c0);
            float h1 = sigm(o1) * tanhf(c1);
            hs0[j] = h0; hs1[j] = h1;
            xe0[(size_t)t * H_ + j] = h0;
            xe1[(size_t)t * H_ + j] = h1;
        }
        __syncthreads();
    }
}

// ==================================================================
extern "C" void kernel_launch(void* const* d_in, const int* in_sizes, int n_in,
                              void* d_out, int out_size){
    const float* X      = (const float*)d_in[0];
    const float* attn_w = (const float*)d_in[1];
    // d_in[2] = attn_b : dead (softmax shift-invariance)
    const float* w_ih   = (const float*)d_in[3];
    const float* w_hh   = (const float*)d_in[4];
    const float* b_ih   = (const float*)d_in[5];
    const float* b_hh   = (const float*)d_in[6];
    float* outXt = (float*)d_out;
    float* outXe = outXt + (size_t)B_ * T_ * N_;

    cudaFuncSetAttribute(k_gemm, cudaFuncAttributeMaxDynamicSharedMemorySize, SM_K3);
    cudaFuncSetAttribute(k_rec,  cudaFuncAttributeMaxDynamicSharedMemorySize, K4_SMEM);

    k_alpha <<<B_, 512>>>(X, attn_w);
    k_wsplit<<<(GATE * N_) / 256, 256>>>(w_ih);
    k_xt    <<<(MTOT * N_ / 4) / 256, 256>>>((const float4*)X, (float4*)outXt);
    k_gemm  <<<dim3(4, 256), 256, SM_K3>>>();
    k_rec   <<<B_ / 2, 512, K4_SMEM>>>(w_hh, b_ih, b_hh, outXe);
}

// round 7
// speedup vs baseline: 1.0859x; 1.0859x over previous
#include <cuda_runtime.h>
#include <cuda_bf16.h>
#include <cstdint>

#define B_ 256
#define T_ 128
#define N_ 512
#define H_ 128
#define MTOT (B_*T_)   /* 32768 */
#define GATE (4*H_)    /* 512 */

// ---------------- scratch (device globals: no allocation allowed) ----------------
__device__ __nv_bfloat16  g_Ah[MTOT*N_];
__device__ __nv_bfloat16  g_Al[MTOT*N_];
__device__ __nv_bfloat16  g_Wh[GATE*N_];
__device__ __nv_bfloat16  g_Wl[GATE*N_];
__device__ float          g_G[(size_t)MTOT*GATE];

// ---------------- helpers ----------------
__device__ __forceinline__ uint32_t smem_u32(const void* p){
    uint32_t a;
    asm("{ .reg .u64 t; cvta.to.shared.u64 t, %1; cvt.u32.u64 %0, t; }" : "=r"(a) : "l"(p));
    return a;
}
__device__ __forceinline__ unsigned long long fma2(unsigned long long a,
                                                   unsigned long long b,
                                                   unsigned long long c){
    unsigned long long d;
    asm("fma.rn.f32x2 %0, %1, %2, %3;" : "=l"(d) : "l"(a), "l"(b), "l"(c));
    return d;
}
__device__ __forceinline__ unsigned long long pack2(float x, float y){
    unsigned long long u;
    asm("mov.b64 %0, {%1, %2};" : "=l"(u) : "f"(x), "f"(y));
    return u;
}
__device__ __forceinline__ float2 unpack2(unsigned long long u){
    float2 v;
    asm("mov.b64 {%0, %1}, %2;" : "=f"(v.x), "=f"(v.y) : "l"(u));
    return v;
}
__device__ __forceinline__ float sigm(float x){ return 1.f / (1.f + __expf(-x)); }

#define LDSM4(r0, r1, r2, r3, addr) \
    asm volatile("ldmatrix.sync.aligned.m8n8.x4.shared.b16 {%0,%1,%2,%3}, [%4];" \
                 : "=r"(r0), "=r"(r1), "=r"(r2), "=r"(r3) : "r"(addr))

#define MMA16816(c, a, b0, b1) \
    asm volatile("mma.sync.aligned.m16n8k16.row.col.f32.bf16.bf16.f32 " \
                 "{%0,%1,%2,%3}, {%4,%5,%6,%7}, {%8,%9}, {%0,%1,%2,%3};" \
                 : "+f"((c)[0]), "+f"((c)[1]), "+f"((c)[2]), "+f"((c)[3]) \
                 : "r"((a)[0]), "r"((a)[1]), "r"((a)[2]), "r"((a)[3]), \
                   "r"(b0), "r"(b1))

__device__ __forceinline__ void cp16(uint32_t s, const void* g){
    asm volatile("cp.async.cg.shared.global [%0], [%1], 16;" :: "r"(s), "l"(g));
}
__device__ __forceinline__ void cp_commit(){
    asm volatile("cp.async.commit_group;" ::: "memory");
}
template<int N> __device__ __forceinline__ void cp_wait(){
    asm volatile("cp.async.wait_group %0;" :: "n"(N) : "memory");
}

// ==================================================================
// K1: fused alpha + Xt.
// alpha[b,n] = softmax_n( sum_t X[b,t,n]*w_x[t] )  (time-invariant:
// score = x_score + per-batch scalar; softmax shift-invariance kills the
// h/c terms; attn_b, w_h, w_s are dead inputs).
// Then Xt = alpha*X (fp32 output) + bf16 hi/lo split copies for the GEMM.
// Phase-2 X reads hit L2 (batch = 256KB, just read in phase 1).
// ==================================================================
__global__ void __launch_bounds__(512) k_fused(const float* __restrict__ X,
                                               const float* __restrict__ attn_w,
                                               float* __restrict__ outXt){
    __shared__ float wx[T_];
    __shared__ float red[N_];
    __shared__ float al[N_];
    int b = blockIdx.x, tid = threadIdx.x;
    if (tid < T_) wx[tid] = attn_w[2 * H_ + tid];
    __syncthreads();
    const float* xb = X + (size_t)b * T_ * N_;
    float s = 0.f;
#pragma unroll 8
    for (int t = 0; t < T_; t++) s += xb[(size_t)t * N_ + tid] * wx[t];
    red[tid] = s; __syncthreads();
    for (int off = N_ / 2; off > 0; off >>= 1){
        if (tid < off){ float o = red[tid + off]; if (o > red[tid]) red[tid] = o; }
        __syncthreads();
    }
    float mx = red[0]; __syncthreads();
    float e = __expf(s - mx);
    red[tid] = e; __syncthreads();
    for (int off = N_ / 2; off > 0; off >>= 1){
        if (tid < off) red[tid] += red[tid + off];
        __syncthreads();
    }
    al[tid] = e / red[0];
    __syncthreads();

    // phase 2: 8 columns per thread, 8 rows per sweep, 16 sweeps
    int n8 = (tid & 63) * 8;
    int rs = tid >> 6;
    float4 a0 = *(float4*)(al + n8);
    float4 a1 = *(float4*)(al + n8 + 4);
    float* xtb = outXt + (size_t)b * T_ * N_;
    __nv_bfloat16* ahb = g_Ah + (size_t)b * T_ * N_;
    __nv_bfloat16* alb = g_Al + (size_t)b * T_ * N_;
#pragma unroll 4
    for (int it = 0; it < 16; it++){
        int row = it * 8 + rs;
        const float4* xr = (const float4*)(xb + (size_t)row * N_ + n8);
        float4 x0 = xr[0], x1 = xr[1];
        float4 r0 = make_float4(a0.x * x0.x, a0.y * x0.y, a0.z * x0.z, a0.w * x0.w);
        float4 r1 = make_float4(a1.x * x1.x, a1.y * x1.y, a1.z * x1.z, a1.w * x1.w);
        float4* xw = (float4*)(xtb + (size_t)row * N_ + n8);
        xw[0] = r0; xw[1] = r1;
        float rv[8] = {r0.x, r0.y, r0.z, r0.w, r1.x, r1.y, r1.z, r1.w};
        __nv_bfloat16 hi[8], lo[8];
#pragma unroll
        for (int i = 0; i < 8; i++){
            hi[i] = __float2bfloat16_rn(rv[i]);
            lo[i] = __float2bfloat16_rn(rv[i] - __bfloat162float(hi[i]));
        }
        union { __nv_bfloat162 h2[4]; uint4 u; } uh, ul;
#pragma unroll
        for (int i = 0; i < 4; i++){
            uh.h2[i] = __halves2bfloat162(hi[2 * i], hi[2 * i + 1]);
            ul.h2[i] = __halves2bfloat162(lo[2 * i], lo[2 * i + 1]);
        }
        *(uint4*)(ahb + (size_t)row * N_ + n8) = uh.u;
        *(uint4*)(alb + (size_t)row * N_ + n8) = ul.u;
    }
}

// ==================================================================
// K2b: bf16 hi/lo split of w_ih
// ==================================================================
__global__ void k_wsplit(const float* __restrict__ w){
    int i = blockIdx.x * blockDim.x + threadIdx.x;  // 512*512 total
    float v = w[i];
    __nv_bfloat16 h = __float2bfloat16_rn(v);
    g_Wh[i] = h;
    g_Wl[i] = __float2bfloat16_rn(v - __bfloat162float(h));
}

// ==================================================================
// K3: G = Xt @ w_ih^T via mma.sync bf16 (HMMA), hi/lo compensated
//     (AhBh + AlBh + AhBl). CTA tile 128x128, K-chunk 32,
//     5-stage cp.async ring, ONE __syncthreads per K-chunk.
//     smem rows: 32 bf16 = 64B at pitch 80B -> conflict-free ldmatrix.
// ==================================================================
#define TILE_B  (128*80)       /* 10240 bytes per tile */
#define STAGE_B (4*TILE_B)     /* 40960 bytes per stage */
#define NSTAGE  5
#define SM_K3   (NSTAGE*STAGE_B)  /* 204800 */

__device__ __forceinline__ void cp_tile(uint32_t sdst, const __nv_bfloat16* __restrict__ g,
                                        int row0, int kc, int tid){
#pragma unroll
    for (int i = 0; i < 2; i++){
        int id = tid + i * 256;            // 512 x 16B chunks
        int row = id >> 2, c = id & 3;
        cp16(sdst + row * 80 + c * 16,
             g + (size_t)(row0 + row) * 512 + kc * 32 + c * 8);
    }
}
__device__ __forceinline__ void cp_stage(uint32_t sbase, int mt, int nt, int kc, int tid){
    cp_tile(sbase,              g_Ah, mt * 128, kc, tid);
    cp_tile(sbase + TILE_B,     g_Al, mt * 128, kc, tid);
    cp_tile(sbase + 2 * TILE_B, g_Wh, nt * 128, kc, tid);
    cp_tile(sbase + 3 * TILE_B, g_Wl, nt * 128, kc, tid);
}

__global__ void __launch_bounds__(256, 1) k_gemm(){
    extern __shared__ char sm[];
    uint32_t smb = smem_u32(sm);
    int tid = threadIdx.x, lane = tid & 31, wid = tid >> 5;
    int nt = blockIdx.x, mt = blockIdx.y;      // x fastest: 4 nt share A panel in L2
    int wm = wid & 3, wn = wid >> 2;           // 4 m-warps x 2 n-warps
    int m0 = wm * 32, n0 = wn * 64;

    float C[2][8][4];
#pragma unroll
    for (int a = 0; a < 2; a++)
#pragma unroll
        for (int b = 0; b < 8; b++)
#pragma unroll
            for (int c = 0; c < 4; c++) C[a][b][c] = 0.f;

    // prologue: stages 0..2 in flight (one commit group each)
#pragma unroll
    for (int s = 0; s < 3; s++){
        cp_stage(smb + s * STAGE_B, mt, nt, s, tid);
        cp_commit();
    }

    // per-lane ldmatrix address components
    int arow  = m0 + (lane & 15);
    int akoff = (lane & 16) ? 16 : 0;
    int nrow  = n0 + (lane & 7) + ((lane & 16) ? 8 : 0);
    int bkoff = (lane & 8) ? 16 : 0;

    for (int kc = 0; kc < 16; kc++){
        // prefetch stage kc+3 into ring slot (kc+3)%5 — that buffer was
        // consumed at iteration kc-2, and every warp crossed the barriers of
        // iterations kc-1 and kc since, so the overwrite is safe with a
        // single barrier per iteration.
        if (kc + 3 < 16) cp_stage(smb + ((kc + 3) % NSTAGE) * STAGE_B, mt, nt, kc + 3, tid);
        cp_commit();
        cp_wait<3>();          // 3 newest groups pending = stages kc+1..kc+3
        __syncthreads();

        uint32_t sA  = smb + (kc % NSTAGE) * STAGE_B;
        uint32_t sAl = sA + TILE_B;
        uint32_t sBh = sA + 2 * TILE_B;
        uint32_t sBl = sA + 3 * TILE_B;

#pragma unroll
        for (int ks = 0; ks < 2; ks++){
            uint32_t ah[2][4], al[2][4];
            uint32_t ka = ks * 32 + akoff;
            LDSM4(ah[0][0], ah[0][1], ah[0][2], ah[0][3], sA  + arow * 80 + ka);
            LDSM4(ah[1][0], ah[1][1], ah[1][2], ah[1][3], sA  + (arow + 16) * 80 + ka);
            LDSM4(al[0][0], al[0][1], al[0][2], al[0][3], sAl + arow * 80 + ka);
            LDSM4(al[1][0], al[1][1], al[1][2], al[1][3], sAl + (arow + 16) * 80 + ka);
            uint32_t kb = ks * 32 + bkoff;
#pragma unroll
            for (int nbp = 0; nbp < 4; nbp++){
                uint32_t bh[4], bl[4];
                uint32_t boff = (nrow + nbp * 16) * 80 + kb;
                LDSM4(bh[0], bh[1], bh[2], bh[3], sBh + boff);
                LDSM4(bl[0], bl[1], bl[2], bl[3], sBl + boff);
#pragma unroll
                for (int mb = 0; mb < 2; mb++){
                    MMA16816(C[mb][nbp * 2],     ah[mb], bh[0], bh[1]);
                    MMA16816(C[mb][nbp * 2],     al[mb], bh[0], bh[1]);
                    MMA16816(C[mb][nbp * 2],     ah[mb], bl[0], bl[1]);
                    MMA16816(C[mb][nbp * 2 + 1], ah[mb], bh[2], bh[3]);
                    MMA16816(C[mb][nbp * 2 + 1], al[mb], bh[2], bh[3]);
                    MMA16816(C[mb][nbp * 2 + 1], ah[mb], bl[2], bl[3]);
                }
            }
        }
    }

    // epilogue: C -> g_G
    int rbase = mt * 128 + m0 + (lane >> 2);
    int cbase = nt * 128 + n0 + (lane & 3) * 2;
#pragma unroll
    for (int mb = 0; mb < 2; mb++){
#pragma unroll
        for (int na = 0; na < 8; na++){
            float* p0 = g_G + (size_t)(rbase + mb * 16) * 512 + cbase + na * 8;
            float* p1 = p0 + 8 * 512;
            *(float2*)p0 = make_float2(C[mb][na][0], C[mb][na][1]);
            *(float2*)p1 = make_float2(C[mb][na][2], C[mb][na][3]);
        }
    }
}

// ==================================================================
// K4: recurrence. 128 CTAs x 2 batches, 256 threads.
//     Thread owns gates j0=2*tid, j0+1 for both batches:
//     256 fma2/thread/step -> SMSP issue floor 1024 cyc/step.
//     w_hh: k 0..31 of both rows in a thread-private smem block
//     (pitch 68 floats -> conflict-free quarter-warp LDS.128 phases),
//     k 32..127 in registers (96 x u64). Crossbar/step =
//     8 warps x (16 LDS.128 + 64 bcast) = 1024 cyc = FMA floor.
// ==================================================================
#define RW_PITCH 68
#define K4_SMEM ((256*RW_PITCH + 128 + 128 + 512 + 512) * 4)

__global__ void __launch_bounds__(256, 1) k_rec(const float* __restrict__ whh,
                                                const float* __restrict__ b_ih,
                                                const float* __restrict__ b_hh,
                                                float* __restrict__ Xe){
    extern __shared__ float smf[];
    float* ws  = smf;                      // 256*68
    float* hs0 = smf + 256 * RW_PITCH;     // 128
    float* hs1 = hs0 + 128;                // 128
    float* gs0 = hs1 + 128;                // 512
    float* gs1 = gs0 + 512;                // 512
    int tid = threadIdx.x;
    int j0 = 2 * tid;
    int b0 = blockIdx.x * 2, b1 = b0 + 1;

    // smem w: rows j0, j0+1, k 0..31 packed per-thread
#pragma unroll
    for (int k = 0; k < 32; k++){
        ws[tid * RW_PITCH + k]      = whh[(size_t)j0 * 128 + k];
        ws[tid * RW_PITCH + 32 + k] = whh[(size_t)(j0 + 1) * 128 + k];
    }
    // reg w: rows j0, j0+1, k 32..127 (48 u64 each)
    unsigned long long wr0[48], wr1[48];
    {
        const float2* p0 = (const float2*)(whh + (size_t)j0 * 128 + 32);
        const float2* p1 = (const float2*)(whh + (size_t)(j0 + 1) * 128 + 32);
#pragma unroll
        for (int i = 0; i < 48; i++){
            float2 v0 = p0[i], v1 = p1[i];
            wr0[i] = pack2(v0.x, v0.y);
            wr1[i] = pack2(v1.x, v1.y);
        }
    }
    float bias0 = b_ih[j0] + b_hh[j0];
    float bias1 = b_ih[j0 + 1] + b_hh[j0 + 1];
    float c0 = 0.f, c1 = 0.f;
    if (tid < 128){ hs0[tid] = 0.f; hs1[tid] = 0.f; }
    __syncthreads();

    const ulonglong2* wsv = (const ulonglong2*)(ws + (size_t)tid * RW_PITCH);
    const ulonglong2* h0v = (const ulonglong2*)hs0;
    const ulonglong2* h1v = (const ulonglong2*)hs1;
    const float* Gb0 = g_G + (size_t)b0 * T_ * 512 + j0;
    const float* Gb1 = g_G + (size_t)b1 * T_ * 512 + j0;
    float* xe0 = Xe + (size_t)b0 * T_ * H_;
    float* xe1 = Xe + (size_t)b1 * T_ * H_;

    for (int t = 0; t < T_; t++){
        float2 gv0 = *(const float2*)(Gb0 + (size_t)t * 512);
        float2 gv1 = *(const float2*)(Gb1 + (size_t)t * 512);
        unsigned long long a00 = 0ull, a10 = 0ull, a01 = 0ull, a11 = 0ull;
#pragma unroll
        for (int i = 0; i < 8; i++){               // k = 0..31 from smem
            ulonglong2 w0 = wsv[i], w1 = wsv[8 + i];
            ulonglong2 hA = h0v[i], hB = h1v[i];
            a00 = fma2(w0.x, hA.x, a00); a00 = fma2(w0.y, hA.y, a00);
            a10 = fma2(w1.x, hA.x, a10); a10 = fma2(w1.y, hA.y, a10);
            a01 = fma2(w0.x, hB.x, a01); a01 = fma2(w0.y, hB.y, a01);
            a11 = fma2(w1.x, hB.x, a11); a11 = fma2(w1.y, hB.y, a11);
        }
#pragma unroll
        for (int i = 0; i < 24; i++){              // k = 32..127 from regs
            ulonglong2 hA = h0v[8 + i], hB = h1v[8 + i];
            unsigned long long u0 = wr0[2 * i], u1 = wr0[2 * i + 1];
            unsigned long long v0 = wr1[2 * i], v1 = wr1[2 * i + 1];
            a00 = fma2(u0, hA.x, a00); a00 = fma2(u1, hA.y, a00);
            a10 = fma2(v0, hA.x, a10); a10 = fma2(v1, hA.y, a10);
            a01 = fma2(u0, hB.x, a01); a01 = fma2(u1, hB.y, a01);
            a11 = fma2(v0, hB.x, a11); a11 = fma2(v1, hB.y, a11);
        }
        float2 s00 = unpack2(a00), s10 = unpack2(a10);
        float2 s01 = unpack2(a01), s11 = unpack2(a11);
        gs0[j0]     = s00.x + s00.y + gv0.x + bias0;
        gs0[j0 + 1] = s10.x + s10.y + gv0.y + bias1;
        gs1[j0]     = s01.x + s01.y + gv1.x + bias0;
        gs1[j0 + 1] = s11.x + s11.y + gv1.y + bias1;
        __syncthreads();
        if (tid < 128){
            int j = tid;
            float i0 = gs0[j], f0 = gs0[j + 128], g0 = gs0[j + 256], o0 = gs0[j + 384];
            float i1 = gs1[j], f1 = gs1[j + 128], g1 = gs1[j + 256], o1 = gs1[j + 384];
            c0 = sigm(f0) * c0 + sigm(i0) * tanhf(g0);
            c1 = sigm(f1) * c1 + sigm(i1) * tanhf(g1);
            float h0 = sigm(o0) * tanhf(c0);
            float h1 = sigm(o1) * tanhf(c1);
            hs0[j] = h0; hs1[j] = h1;
            xe0[(size_t)t * H_ + j] = h0;
            xe1[(size_t)t * H_ + j] = h1;
        }
        __syncthreads();
    }
}

// ==================================================================
extern "C" void kernel_launch(void* const* d_in, const int* in_sizes, int n_in,
                              void* d_out, int out_size){
    const float* X      = (const float*)d_in[0];
    const float* attn_w = (const float*)d_in[1];
    // d_in[2] = attn_b : dead (softmax shift-invariance)
    const float* w_ih   = (const float*)d_in[3];
    const float* w_hh   = (const float*)d_in[4];
    const float* b_ih   = (const float*)d_in[5];
    const float* b_hh   = (const float*)d_in[6];
    float* outXt = (float*)d_out;
    float* outXe = outXt + (size_t)B_ * T_ * N_;

    cudaFuncSetAttribute(k_gemm, cudaFuncAttributeMaxDynamicSharedMemorySize, SM_K3);
    cudaFuncSetAttribute(k_rec,  cudaFuncAttributeMaxDynamicSharedMemorySize, K4_SMEM);

    k_wsplit<<<(GATE * N_) / 256, 256>>>(w_ih);
    k_fused <<<B_, 512>>>(X, attn_w, outXt);
    k_gemm  <<<dim3(4, 256), 256, SM_K3>>>();
    k_rec   <<<B_ / 2, 256, K4_SMEM>>>(w_hh, b_ih, b_hh, outXe);
}

// round 8
// speedup vs baseline: 1.2246x; 1.1277x over previous
#include <cuda_runtime.h>
#include <cuda_bf16.h>
#include <cstdint>

#define B_ 256
#define T_ 128
#define N_ 512
#define H_ 128
#define MTOT (B_*T_)   /* 32768 */
#define GATE (4*H_)    /* 512 */

// ---------------- scratch (device globals: no allocation allowed) ----------------
__device__ __nv_bfloat16  g_Ah[MTOT*N_];
__device__ __nv_bfloat16  g_Al[MTOT*N_];
__device__ __nv_bfloat16  g_Wh[GATE*N_];
__device__ __nv_bfloat16  g_Wl[GATE*N_];
__device__ float          g_G[(size_t)MTOT*GATE];

// ---------------- helpers ----------------
__device__ __forceinline__ uint32_t smem_u32(const void* p){
    uint32_t a;
    asm("{ .reg .u64 t; cvta.to.shared.u64 t, %1; cvt.u32.u64 %0, t; }" : "=r"(a) : "l"(p));
    return a;
}
__device__ __forceinline__ unsigned long long fma2(unsigned long long a,
                                                   unsigned long long b,
                                                   unsigned long long c){
    unsigned long long d;
    asm("fma.rn.f32x2 %0, %1, %2, %3;" : "=l"(d) : "l"(a), "l"(b), "l"(c));
    return d;
}
__device__ __forceinline__ unsigned long long pack2(float x, float y){
    unsigned long long u;
    asm("mov.b64 %0, {%1, %2};" : "=l"(u) : "f"(x), "f"(y));
    return u;
}
__device__ __forceinline__ float2 unpack2(unsigned long long u){
    float2 v;
    asm("mov.b64 {%0, %1}, %2;" : "=f"(v.x), "=f"(v.y) : "l"(u));
    return v;
}
__device__ __forceinline__ float sigm(float x){ return 1.f / (1.f + __expf(-x)); }

#define LDSM4(r0, r1, r2, r3, addr) \
    asm volatile("ldmatrix.sync.aligned.m8n8.x4.shared.b16 {%0,%1,%2,%3}, [%4];" \
                 : "=r"(r0), "=r"(r1), "=r"(r2), "=r"(r3) : "r"(addr))

#define MMA16816(c, a, b0, b1) \
    asm volatile("mma.sync.aligned.m16n8k16.row.col.f32.bf16.bf16.f32 " \
                 "{%0,%1,%2,%3}, {%4,%5,%6,%7}, {%8,%9}, {%0,%1,%2,%3};" \
                 : "+f"((c)[0]), "+f"((c)[1]), "+f"((c)[2]), "+f"((c)[3]) \
                 : "r"((a)[0]), "r"((a)[1]), "r"((a)[2]), "r"((a)[3]), \
                   "r"(b0), "r"(b1))

__device__ __forceinline__ void cp16(uint32_t s, const void* g){
    asm volatile("cp.async.cg.shared.global [%0], [%1], 16;" :: "r"(s), "l"(g));
}
__device__ __forceinline__ void cp_commit(){
    asm volatile("cp.async.commit_group;" ::: "memory");
}
template<int N> __device__ __forceinline__ void cp_wait(){
    asm volatile("cp.async.wait_group %0;" :: "n"(N) : "memory");
}

// ==================================================================
// K1: fused alpha + Xt. (unchanged from R7)
// alpha[b,n] = softmax_n( sum_t X[b,t,n]*w_x[t] )  (time-invariant:
// score = x_score + per-batch scalar; softmax shift-invariance kills the
// h/c terms; attn_b, w_h, w_s are dead inputs).
// ==================================================================
__global__ void __launch_bounds__(512) k_fused(const float* __restrict__ X,
                                               const float* __restrict__ attn_w,
                                               float* __restrict__ outXt){
    __shared__ float wx[T_];
    __shared__ float red[N_];
    __shared__ float al[N_];
    int b = blockIdx.x, tid = threadIdx.x;
    if (tid < T_) wx[tid] = attn_w[2 * H_ + tid];
    __syncthreads();
    const float* xb = X + (size_t)b * T_ * N_;
    float s = 0.f;
#pragma unroll 8
    for (int t = 0; t < T_; t++) s += xb[(size_t)t * N_ + tid] * wx[t];
    red[tid] = s; __syncthreads();
    for (int off = N_ / 2; off > 0; off >>= 1){
        if (tid < off){ float o = red[tid + off]; if (o > red[tid]) red[tid] = o; }
        __syncthreads();
    }
    float mx = red[0]; __syncthreads();
    float e = __expf(s - mx);
    red[tid] = e; __syncthreads();
    for (int off = N_ / 2; off > 0; off >>= 1){
        if (tid < off) red[tid] += red[tid + off];
        __syncthreads();
    }
    al[tid] = e / red[0];
    __syncthreads();

    int n8 = (tid & 63) * 8;
    int rs = tid >> 6;
    float4 a0 = *(float4*)(al + n8);
    float4 a1 = *(float4*)(al + n8 + 4);
    float* xtb = outXt + (size_t)b * T_ * N_;
    __nv_bfloat16* ahb = g_Ah + (size_t)b * T_ * N_;
    __nv_bfloat16* alb = g_Al + (size_t)b * T_ * N_;
#pragma unroll 4
    for (int it = 0; it < 16; it++){
        int row = it * 8 + rs;
        const float4* xr = (const float4*)(xb + (size_t)row * N_ + n8);
        float4 x0 = xr[0], x1 = xr[1];
        float4 r0 = make_float4(a0.x * x0.x, a0.y * x0.y, a0.z * x0.z, a0.w * x0.w);
        float4 r1 = make_float4(a1.x * x1.x, a1.y * x1.y, a1.z * x1.z, a1.w * x1.w);
        float4* xw = (float4*)(xtb + (size_t)row * N_ + n8);
        xw[0] = r0; xw[1] = r1;
        float rv[8] = {r0.x, r0.y, r0.z, r0.w, r1.x, r1.y, r1.z, r1.w};
        __nv_bfloat16 hi[8], lo[8];
#pragma unroll
        for (int i = 0; i < 8; i++){
            hi[i] = __float2bfloat16_rn(rv[i]);
            lo[i] = __float2bfloat16_rn(rv[i] - __bfloat162float(hi[i]));
        }
        union { __nv_bfloat162 h2[4]; uint4 u; } uh, ul;
#pragma unroll
        for (int i = 0; i < 4; i++){
            uh.h2[i] = __halves2bfloat162(hi[2 * i], hi[2 * i + 1]);
            ul.h2[i] = __halves2bfloat162(lo[2 * i], lo[2 * i + 1]);
        }
        *(uint4*)(ahb + (size_t)row * N_ + n8) = uh.u;
        *(uint4*)(alb + (size_t)row * N_ + n8) = ul.u;
    }
}

// ==================================================================
// K2b: bf16 hi/lo split of w_ih (unchanged)
// ==================================================================
__global__ void k_wsplit(const float* __restrict__ w){
    int i = blockIdx.x * blockDim.x + threadIdx.x;
    float v = w[i];
    __nv_bfloat16 h = __float2bfloat16_rn(v);
    g_Wh[i] = h;
    g_Wl[i] = __float2bfloat16_rn(v - __bfloat162float(h));
}

// ==================================================================
// K3: G = Xt @ w_ih^T, hi/lo compensated HMMA. (unchanged from R7)
// ==================================================================
#define TILE_B  (128*80)
#define STAGE_B (4*TILE_B)
#define NSTAGE  5
#define SM_K3   (NSTAGE*STAGE_B)

__device__ __forceinline__ void cp_tile(uint32_t sdst, const __nv_bfloat16* __restrict__ g,
                                        int row0, int kc, int tid){
#pragma unroll
    for (int i = 0; i < 2; i++){
        int id = tid + i * 256;
        int row = id >> 2, c = id & 3;
        cp16(sdst + row * 80 + c * 16,
             g + (size_t)(row0 + row) * 512 + kc * 32 + c * 8);
    }
}
__device__ __forceinline__ void cp_stage(uint32_t sbase, int mt, int nt, int kc, int tid){
    cp_tile(sbase,              g_Ah, mt * 128, kc, tid);
    cp_tile(sbase + TILE_B,     g_Al, mt * 128, kc, tid);
    cp_tile(sbase + 2 * TILE_B, g_Wh, nt * 128, kc, tid);
    cp_tile(sbase + 3 * TILE_B, g_Wl, nt * 128, kc, tid);
}

__global__ void __launch_bounds__(256, 1) k_gemm(){
    extern __shared__ char sm[];
    uint32_t smb = smem_u32(sm);
    int tid = threadIdx.x, lane = tid & 31, wid = tid >> 5;
    int nt = blockIdx.x, mt = blockIdx.y;
    int wm = wid & 3, wn = wid >> 2;
    int m0 = wm * 32, n0 = wn * 64;

    float C[2][8][4];
#pragma unroll
    for (int a = 0; a < 2; a++)
#pragma unroll
        for (int b = 0; b < 8; b++)
#pragma unroll
            for (int c = 0; c < 4; c++) C[a][b][c] = 0.f;

#pragma unroll
    for (int s = 0; s < 3; s++){
        cp_stage(smb + s * STAGE_B, mt, nt, s, tid);
        cp_commit();
    }

    int arow  = m0 + (lane & 15);
    int akoff = (lane & 16) ? 16 : 0;
    int nrow  = n0 + (lane & 7) + ((lane & 16) ? 8 : 0);
    int bkoff = (lane & 8) ? 16 : 0;

    for (int kc = 0; kc < 16; kc++){
        if (kc + 3 < 16) cp_stage(smb + ((kc + 3) % NSTAGE) * STAGE_B, mt, nt, kc + 3, tid);
        cp_commit();
        cp_wait<3>();
        __syncthreads();

        uint32_t sA  = smb + (kc % NSTAGE) * STAGE_B;
        uint32_t sAl = sA + TILE_B;
        uint32_t sBh = sA + 2 * TILE_B;
        uint32_t sBl = sA + 3 * TILE_B;

#pragma unroll
        for (int ks = 0; ks < 2; ks++){
            uint32_t ah[2][4], al[2][4];
            uint32_t ka = ks * 32 + akoff;
            LDSM4(ah[0][0], ah[0][1], ah[0][2], ah[0][3], sA  + arow * 80 + ka);
            LDSM4(ah[1][0], ah[1][1], ah[1][2], ah[1][3], sA  + (arow + 16) * 80 + ka);
            LDSM4(al[0][0], al[0][1], al[0][2], al[0][3], sAl + arow * 80 + ka);
            LDSM4(al[1][0], al[1][1], al[1][2], al[1][3], sAl + (arow + 16) * 80 + ka);
            uint32_t kb = ks * 32 + bkoff;
#pragma unroll
            for (int nbp = 0; nbp < 4; nbp++){
                uint32_t bh[4], bl[4];
                uint32_t boff = (nrow + nbp * 16) * 80 + kb;
                LDSM4(bh[0], bh[1], bh[2], bh[3], sBh + boff);
                LDSM4(bl[0], bl[1], bl[2], bl[3], sBl + boff);
#pragma unroll
                for (int mb = 0; mb < 2; mb++){
                    MMA16816(C[mb][nbp * 2],     ah[mb], bh[0], bh[1]);
                    MMA16816(C[mb][nbp * 2],     al[mb], bh[0], bh[1]);
                    MMA16816(C[mb][nbp * 2],     ah[mb], bl[0], bl[1]);
                    MMA16816(C[mb][nbp * 2 + 1], ah[mb], bh[2], bh[3]);
                    MMA16816(C[mb][nbp * 2 + 1], al[mb], bh[2], bh[3]);
                    MMA16816(C[mb][nbp * 2 + 1], ah[mb], bl[2], bl[3]);
                }
            }
        }
    }

    int rbase = mt * 128 + m0 + (lane >> 2);
    int cbase = nt * 128 + n0 + (lane & 3) * 2;
#pragma unroll
    for (int mb = 0; mb < 2; mb++){
#pragma unroll
        for (int na = 0; na < 8; na++){
            float* p0 = g_G + (size_t)(rbase + mb * 16) * 512 + cbase + na * 8;
            float* p1 = p0 + 8 * 512;
            *(float2*)p0 = make_float2(C[mb][na][0], C[mb][na][1]);
            *(float2*)p1 = make_float2(C[mb][na][2], C[mb][na][3]);
        }
    }
}

// ==================================================================
// K4: recurrence, REBALANCED to kill register spills (R7: regs=255,
// L1 37.7% = LDL spill traffic, fma 22.5%).
// 128 CTAs x 2 batches, 256 threads, thread = gates (2t, 2t+1) x 2 batches.
// Weights: k 0..63 in regs (64 u64 = 128 regs, total ~175 -> NO spill),
//          k 64..127 in smem thread-private blocks, pitch 132 floats
//          (33 = 1 mod 8 -> LDS.128 phases hit 8 distinct bank groups).
// Per step per SM: fma pipe 2048 fma2 / 2 = 1024 cyc; crossbar 128KB
// / 128B/cyc = 1024 cyc (parallel pipes). Cell phase over ALL 256
// threads (thread = (hidden j, batch), c thread-resident).
// ==================================================================
#define RW_PITCH 132
#define K4_SMEM ((256*RW_PITCH + 128 + 128 + 512 + 512) * 4)

__global__ void __launch_bounds__(256, 1) k_rec(const float* __restrict__ whh,
                                                const float* __restrict__ b_ih,
                                                const float* __restrict__ b_hh,
                                                float* __restrict__ Xe){
    extern __shared__ float smf[];
    float* ws  = smf;                      // 256*132
    float* hs0 = smf + 256 * RW_PITCH;     // 128
    float* hs1 = hs0 + 128;                // 128
    float* gs0 = hs1 + 128;                // 512
    float* gs1 = gs0 + 512;                // 512
    int tid = threadIdx.x;
    int j0 = 2 * tid;
    int b0 = blockIdx.x * 2, b1 = b0 + 1;

    // regs: rows j0, j0+1, k 0..63  (32 u64 each = 128 regs total)
    unsigned long long wr0[32], wr1[32];
    {
        const float2* p0 = (const float2*)(whh + (size_t)j0 * 128);
        const float2* p1 = (const float2*)(whh + (size_t)(j0 + 1) * 128);
#pragma unroll
        for (int i = 0; i < 32; i++){
            float2 v0 = p0[i], v1 = p1[i];
            wr0[i] = pack2(v0.x, v0.y);
            wr1[i] = pack2(v1.x, v1.y);
        }
    }
    // smem: rows j0, j0+1, k 64..127 (thread-private 128-float block)
#pragma unroll
    for (int k = 0; k < 64; k++){
        ws[tid * RW_PITCH + k]      = whh[(size_t)j0 * 128 + 64 + k];
        ws[tid * RW_PITCH + 64 + k] = whh[(size_t)(j0 + 1) * 128 + 64 + k];
    }
    float bias0 = b_ih[j0] + b_hh[j0];
    float bias1 = b_ih[j0 + 1] + b_hh[j0 + 1];
    if (tid < 128) hs0[tid] = 0.f; else hs1[tid - 128] = 0.f;
    __syncthreads();

    const ulonglong2* wsv = (const ulonglong2*)(ws + (size_t)tid * RW_PITCH);
    const ulonglong2* h0v = (const ulonglong2*)hs0;
    const ulonglong2* h1v = (const ulonglong2*)hs1;
    const float* Gb0 = g_G + (size_t)b0 * T_ * 512 + j0;
    const float* Gb1 = g_G + (size_t)b1 * T_ * 512 + j0;

    // cell-phase mapping: thread = (hidden j, batch bsel)
    int cj = tid & 127, bsel = tid >> 7;
    float* gsb = bsel ? gs1 : gs0;
    float* hsb = bsel ? hs1 : hs0;
    float* xeb = Xe + (size_t)(bsel ? b1 : b0) * T_ * H_ + cj;
    float cc = 0.f;

    for (int t = 0; t < T_; t++){
        float2 gv0 = *(const float2*)(Gb0 + (size_t)t * 512);
        float2 gv1 = *(const float2*)(Gb1 + (size_t)t * 512);
        unsigned long long a00 = 0ull, a10 = 0ull, a01 = 0ull, a11 = 0ull;
#pragma unroll
        for (int i = 0; i < 16; i++){              // k = 0..63 from regs
            ulonglong2 hA = h0v[i], hB = h1v[i];
            unsigned long long u0 = wr0[2 * i], u1 = wr0[2 * i + 1];
            unsigned long long v0 = wr1[2 * i], v1 = wr1[2 * i + 1];
            a00 = fma2(u0, hA.x, a00); a00 = fma2(u1, hA.y, a00);
            a10 = fma2(v0, hA.x, a10); a10 = fma2(v1, hA.y, a10);
            a01 = fma2(u0, hB.x, a01); a01 = fma2(u1, hB.y, a01);
            a11 = fma2(v0, hB.x, a11); a11 = fma2(v1, hB.y, a11);
        }
#pragma unroll
        for (int i = 0; i < 16; i++){              // k = 64..127 from smem
            ulonglong2 w0 = wsv[i], w1 = wsv[16 + i];
            ulonglong2 hA = h0v[16 + i], hB = h1v[16 + i];
            a00 = fma2(w0.x, hA.x, a00); a00 = fma2(w0.y, hA.y, a00);
            a10 = fma2(w1.x, hA.x, a10); a10 = fma2(w1.y, hA.y, a10);
            a01 = fma2(w0.x, hB.x, a01); a01 = fma2(w0.y, hB.y, a01);
            a11 = fma2(w1.x, hB.x, a11); a11 = fma2(w1.y, hB.y, a11);
        }
        float2 s00 = unpack2(a00), s10 = unpack2(a10);
        float2 s01 = unpack2(a01), s11 = unpack2(a11);
        gs0[j0]     = s00.x + s00.y + gv0.x + bias0;
        gs0[j0 + 1] = s10.x + s10.y + gv0.y + bias1;
        gs1[j0]     = s01.x + s01.y + gv1.x + bias0;
        gs1[j0 + 1] = s11.x + s11.y + gv1.y + bias1;
        __syncthreads();
        {
            float iv = gsb[cj], fv = gsb[cj + 128];
            float gv = gsb[cj + 256], ov = gsb[cj + 384];
            cc = sigm(fv) * cc + sigm(iv) * tanhf(gv);
            float hv = sigm(ov) * tanhf(cc);
            hsb[cj] = hv;
            xeb[(size_t)t * H_] = hv;
        }
        __syncthreads();
    }
}

// ==================================================================
extern "C" void kernel_launch(void* const* d_in, const int* in_sizes, int n_in,
                              void* d_out, int out_size){
    const float* X      = (const float*)d_in[0];
    const float* attn_w = (const float*)d_in[1];
    // d_in[2] = attn_b : dead (softmax shift-invariance)
    const float* w_ih   = (const float*)d_in[3];
    const float* w_hh   = (const float*)d_in[4];
    const float* b_ih   = (const float*)d_in[5];
    const float* b_hh   = (const float*)d_in[6];
    float* outXt = (float*)d_out;
    float* outXe = outXt + (size_t)B_ * T_ * N_;

    cudaFuncSetAttribute(k_gemm, cudaFuncAttributeMaxDynamicSharedMemorySize, SM_K3);
    cudaFuncSetAttribute(k_rec,  cudaFuncAttributeMaxDynamicSharedMemorySize, K4_SMEM);

    k_wsplit<<<(GATE * N_) / 256, 256>>>(w_ih);
    k_fused <<<B_, 512>>>(X, attn_w, outXt);
    k_gemm  <<<dim3(4, 256), 256, SM_K3>>>();
    k_rec   <<<B_ / 2, 256, K4_SMEM>>>(w_hh, b_ih, b_hh, outXe);
}